// round 11
// baseline (speedup 1.0000x reference)
#include <cuda_runtime.h>
#include <cuda_bf16.h>
#include <mma.h>
#include <cstdint>

using namespace nvcuda;

// Problem dims (fixed)
#define BATCH 8
#define TLEN  4096
#define IDIM  1024
#define NDIM  64
#define BT    (BATCH * TLEN)      // 32768
#define CH    64                  // scan chunk length (= K1 M tile)
#define NCH   (TLEN / CH)         // 64 chunks per batch

// ---------------------------------------------------------------------------
// Scratch (device globals; allocation forbidden)
// ---------------------------------------------------------------------------
__device__ __nv_bfloat16 g_Bb[NDIM * IDIM];      // Bbar bf16 [n][k]
__device__ __nv_bfloat16 g_Cb[IDIM * NDIM];      // C bf16 [i][n]
__device__ float g_a[NDIM];                      // A_bar_state
__device__ float g_Bu[(size_t)BT * NDIM];        // locally-scanned x (8 MB)
__device__ float g_end[BATCH * NCH * NDIM];      // chunk-local end states
__device__ float g_carry[BATCH * NCH * NDIM];    // carry-in per chunk
__device__ float g_apow[CH * NDIM];              // a_n^(t+1), t=0..63

// ---------------------------------------------------------------------------
// K0 (fused): blocks 0..63  -> per-n: Bbar=B*softplus(logdelta) bf16, a_n
//             blocks 64..127 -> convert C to bf16
// ---------------------------------------------------------------------------
__global__ void k_setup(const float* __restrict__ logA,
                        const float* __restrict__ B,
                        const float* __restrict__ C,
                        const float* __restrict__ logdelta) {
    if (blockIdx.x < NDIM) {
        int n = blockIdx.x;
        float A = -expf(logA[n]);
        __shared__ float red[256];
        float s = 0.f;
        for (int i = threadIdx.x; i < IDIM; i += 256) {
            float ld = logdelta[i];
            float d  = (ld > 20.f) ? ld : log1pf(expf(ld));
            g_Bb[n * IDIM + i] = __float2bfloat16_rn(B[n * IDIM + i] * d);
            s += expf(d * A);
        }
        red[threadIdx.x] = s;
        __syncthreads();
        for (int o = 128; o > 0; o >>= 1) {
            if (threadIdx.x < o) red[threadIdx.x] += red[threadIdx.x + o];
            __syncthreads();
        }
        if (threadIdx.x == 0) g_a[n] = red[0] * (1.f / IDIM);
    } else {
        int idx = (blockIdx.x - NDIM) * 256 + threadIdx.x;
        float4 v = *reinterpret_cast<const float4*>(C + 4 * (size_t)idx);
        __nv_bfloat162 lo = __floats2bfloat162_rn(v.x, v.y);
        __nv_bfloat162 hi = __floats2bfloat162_rn(v.z, v.w);
        uint2 pk = make_uint2(*reinterpret_cast<unsigned*>(&lo),
                              *reinterpret_cast<unsigned*>(&hi));
        *reinterpret_cast<uint2*>(&g_Cb[4 * (size_t)idx]) = pk;
    }
}

// ---------------------------------------------------------------------------
// K1: wmma GEMM1 + in-smem local scan epilogue. (unchanged from R10)
// ---------------------------------------------------------------------------
#define G1_LDA 72
#define G1_LDY 68
#define G1_AS   0
#define G1_BS   (64 * G1_LDA * 2)            // 9216
#define G1_YBU  0
#define G1_SEG  (64 * G1_LDY * 4)            // 17408
#define G1_SMEM (G1_SEG + 4 * NDIM * 4)      // 18432

__global__ __launch_bounds__(256) void k_gemm1(const float* __restrict__ u) {
    extern __shared__ char smem[];
    __nv_bfloat16* As = reinterpret_cast<__nv_bfloat16*>(smem + G1_AS);
    __nv_bfloat16* Bs = reinterpret_cast<__nv_bfloat16*>(smem + G1_BS);
    float*        Ybu = reinterpret_cast<float*>(smem + G1_YBU);
    float*        seg = reinterpret_cast<float*>(smem + G1_SEG);

    const int tid = threadIdx.x;
    const int wid = tid >> 5;
    const int wy  = wid >> 2;                    // 0..1 -> m offset 32*wy
    const int wx  = wid & 3;                     // 0..3 -> n offset 16*wx
    const int m0  = blockIdx.x * 64;
    const float* ub = &u[(size_t)m0 * IDIM];

    wmma::fragment<wmma::accumulator, 16, 16, 16, float> acc[2];
#pragma unroll
    for (int a = 0; a < 2; a++) wmma::fill_fragment(acc[a], 0.f);

    float4 r[4];
#pragma unroll
    for (int q = 0; q < 4; q++) {
        int idx = tid + 256 * q;
        int row = idx >> 4;
        int k   = (idx & 15) << 2;
        r[q] = *reinterpret_cast<const float4*>(&ub[(size_t)row * IDIM + k]);
    }

    for (int kc = 0; kc < IDIM; kc += 64) {
#pragma unroll
        for (int q = 0; q < 4; q++) {
            int idx = tid + 256 * q;
            int row = idx >> 4;
            int k   = (idx & 15) << 2;
            __nv_bfloat162 lo = __floats2bfloat162_rn(r[q].x, r[q].y);
            __nv_bfloat162 hi = __floats2bfloat162_rn(r[q].z, r[q].w);
            uint2 pk = make_uint2(*reinterpret_cast<unsigned*>(&lo),
                                  *reinterpret_cast<unsigned*>(&hi));
            *reinterpret_cast<uint2*>(&As[row * G1_LDA + k]) = pk;
        }
#pragma unroll
        for (int q = 0; q < 4; q++) {
            int idx = tid + 256 * q;
            int n   = idx >> 4;
            int k   = (idx & 15) << 2;
            uint2 pk = *reinterpret_cast<const uint2*>(&g_Bb[n * IDIM + kc + k]);
            *reinterpret_cast<uint2*>(&Bs[n * G1_LDA + k]) = pk;
        }
        __syncthreads();

        if (kc + 64 < IDIM) {
#pragma unroll
            for (int q = 0; q < 4; q++) {
                int idx = tid + 256 * q;
                int row = idx >> 4;
                int k   = (idx & 15) << 2;
                r[q] = *reinterpret_cast<const float4*>(
                    &ub[(size_t)row * IDIM + kc + 64 + k]);
            }
        }

#pragma unroll
        for (int ks = 0; ks < 4; ks++) {
            int k = ks * 16;
            wmma::fragment<wmma::matrix_a, 16, 16, 16, __nv_bfloat16, wmma::row_major> af[2];
            wmma::fragment<wmma::matrix_b, 16, 16, 16, __nv_bfloat16, wmma::col_major> bf;
#pragma unroll
            for (int mi = 0; mi < 2; mi++)
                wmma::load_matrix_sync(af[mi], &As[(wy * 32 + mi * 16) * G1_LDA + k], G1_LDA);
            wmma::load_matrix_sync(bf, &Bs[(wx * 16) * G1_LDA + k], G1_LDA);
#pragma unroll
            for (int mi = 0; mi < 2; mi++)
                wmma::mma_sync(acc[mi], af[mi], bf, acc[mi]);
        }
        __syncthreads();
    }

#pragma unroll
    for (int mi = 0; mi < 2; mi++)
        wmma::store_matrix_sync(&Ybu[(wy * 32 + mi * 16) * G1_LDY + wx * 16],
                                acc[mi], G1_LDY, wmma::mem_row_major);
    __syncthreads();

    const int n = tid & 63, q = tid >> 6;
    const float a = g_a[n];
    {
        float* p = &Ybu[(q * 16) * G1_LDY + n];
        float x = 0.f;
#pragma unroll
        for (int j = 0; j < 16; j++) {
            x = x * a + p[j * G1_LDY];
            p[j * G1_LDY] = x;
        }
        seg[q * 64 + n] = x;
    }
    __syncthreads();
    if (q > 0) {
        float a16 = a;
#pragma unroll
        for (int s = 0; s < 4; s++) a16 *= a16;   // a^16
        float S = seg[n];
        for (int pp = 1; pp < q; pp++) S = S * a16 + seg[pp * 64 + n];
        float f = S;
        float* p = &Ybu[(q * 16) * G1_LDY + n];
#pragma unroll
        for (int j = 0; j < 16; j++) {
            f *= a;
            p[j * G1_LDY] += f;
        }
    }
    __syncthreads();

#pragma unroll
    for (int qq = 0; qq < 4; qq++) {
        int idx = tid + 256 * qq;
        int row = idx >> 4;
        int c4  = (idx & 15) << 2;
        float4 v = *reinterpret_cast<const float4*>(&Ybu[row * G1_LDY + c4]);
        *reinterpret_cast<float4*>(&g_Bu[(size_t)(m0 + row) * NDIM + c4]) = v;
    }
    if (tid < 64) g_end[blockIdx.x * 64 + tid] = Ybu[63 * G1_LDY + tid];
}

// ---------------------------------------------------------------------------
// Kc: blocks 0..7 -> per-batch carry scan over 64 chunks; block 8 -> apow.
// ---------------------------------------------------------------------------
__global__ void k_carry() {
    int n = threadIdx.x;
    if (blockIdx.x < BATCH) {
        int b = blockIdx.x;
        float e[NCH];
#pragma unroll
        for (int c = 0; c < NCH; c++) e[c] = g_end[(b * NCH + c) * 64 + n];
        float a = g_a[n], aL = a;
#pragma unroll
        for (int s = 0; s < 6; s++) aL *= aL;     // a^64 = a^CH
        float carry = 0.f;
#pragma unroll
        for (int c = 0; c < NCH; c++) {
            g_carry[(b * NCH + c) * 64 + n] = carry;
            carry = carry * aL + e[c];
        }
    } else {
        float a = g_a[n], p = a;
        for (int j = 0; j < CH; j++) {
            g_apow[j * 64 + n] = p;               // a^(j+1)
            p *= a;
        }
    }
}

// ---------------------------------------------------------------------------
// K2: raw mma.sync GEMM2 — accumulators stay in registers, no Ys round-trip.
//   256 threads, block tile 128(m) x 64(i); 8 warps (4m x 2i), warp 32x32.
//   Per warp: 2 (mi, m16) x 4 (ni, n8) mma.m16n8k16 tiles.
//   xs[t][n] = x_local + carry[chunk(t)][n]*apow[t%64][n] (bf16 staged in Xs)
//   epilogue: y[r][c] = acc + D[c]*u[r][c] directly from fragment layout.
// smem: Xs[128][72] bf16 (18432) + Cs[64][72] bf16 (9216) = 27648.
// ---------------------------------------------------------------------------
#define G2_LDA 72
#define G2_XS   0
#define G2_CS   18432
#define G2_SMEM 27648

__device__ __forceinline__ void ldm_x4(uint32_t& r0, uint32_t& r1,
                                       uint32_t& r2, uint32_t& r3, uint32_t a) {
    asm volatile("ldmatrix.sync.aligned.m8n8.x4.shared.b16 {%0,%1,%2,%3}, [%4];"
                 : "=r"(r0), "=r"(r1), "=r"(r2), "=r"(r3) : "r"(a));
}
__device__ __forceinline__ void ldm_x2(uint32_t& r0, uint32_t& r1, uint32_t a) {
    asm volatile("ldmatrix.sync.aligned.m8n8.x2.shared.b16 {%0,%1}, [%2];"
                 : "=r"(r0), "=r"(r1) : "r"(a));
}
__device__ __forceinline__ void mma_bf16(float* d, const uint32_t* a,
                                         uint32_t b0, uint32_t b1) {
    asm volatile(
        "mma.sync.aligned.m16n8k16.row.col.f32.bf16.bf16.f32 "
        "{%0,%1,%2,%3}, {%4,%5,%6,%7}, {%8,%9}, {%0,%1,%2,%3};"
        : "+f"(d[0]), "+f"(d[1]), "+f"(d[2]), "+f"(d[3])
        : "r"(a[0]), "r"(a[1]), "r"(a[2]), "r"(a[3]), "r"(b0), "r"(b1));
}

__global__ __launch_bounds__(256) void k_gemm2(const float* __restrict__ u,
                                               const float* __restrict__ D,
                                               float* __restrict__ y) {
    extern __shared__ char smem[];
    __nv_bfloat16* Xs = reinterpret_cast<__nv_bfloat16*>(smem + G2_XS);
    __nv_bfloat16* Cs = reinterpret_cast<__nv_bfloat16*>(smem + G2_CS);

    const int tid  = threadIdx.x;
    const int wid  = tid >> 5;
    const int lane = tid & 31;
    const int wy   = wid >> 1;                   // 0..3 -> m offset 32*wy
    const int wx   = wid & 1;                    // 0..1 -> i offset 32*wx
    const int m0   = blockIdx.x * 128;
    const int i0   = blockIdx.y * 64;
    const int chk2 = blockIdx.x * 2;             // first 64-chunk id in tile

    // xs tile: fixup + bf16 convert (8 float4/thread)
#pragma unroll
    for (int q = 0; q < 8; q++) {
        int idx = tid + 256 * q;
        int row = idx >> 4;                      // 0..127
        int c4  = (idx & 15) << 2;
        float4 bu = *reinterpret_cast<const float4*>(
            &g_Bu[(size_t)(m0 + row) * NDIM + c4]);
        float4 ap = *reinterpret_cast<const float4*>(&g_apow[(row & 63) * 64 + c4]);
        float4 cr = *reinterpret_cast<const float4*>(
            &g_carry[(chk2 + (row >> 6)) * 64 + c4]);
        float x0 = bu.x + cr.x * ap.x;
        float x1 = bu.y + cr.y * ap.y;
        float x2 = bu.z + cr.z * ap.z;
        float x3 = bu.w + cr.w * ap.w;
        __nv_bfloat162 lo = __floats2bfloat162_rn(x0, x1);
        __nv_bfloat162 hi = __floats2bfloat162_rn(x2, x3);
        uint2 pk = make_uint2(*reinterpret_cast<unsigned*>(&lo),
                              *reinterpret_cast<unsigned*>(&hi));
        *reinterpret_cast<uint2*>(&Xs[row * G2_LDA + c4]) = pk;
    }
    // C tile: 64 i-rows x 64 n bf16 (4 uint2/thread)
#pragma unroll
    for (int q = 0; q < 4; q++) {
        int idx = tid + 256 * q;
        int i   = idx >> 4;
        int k   = (idx & 15) << 2;
        uint2 pk = *reinterpret_cast<const uint2*>(&g_Cb[(size_t)(i0 + i) * NDIM + k]);
        *reinterpret_cast<uint2*>(&Cs[i * G2_LDA + k]) = pk;
    }
    __syncthreads();

    float d[2][4][4];
#pragma unroll
    for (int mi = 0; mi < 2; mi++)
#pragma unroll
        for (int ni = 0; ni < 4; ni++)
#pragma unroll
            for (int e = 0; e < 4; e++) d[mi][ni][e] = 0.f;

    const uint32_t xbase = (uint32_t)__cvta_generic_to_shared(Xs);
    const uint32_t cbase = (uint32_t)__cvta_generic_to_shared(Cs);
    // ldmatrix per-lane source rows (A: x4 over 16 rows x 2 k-halves;
    //                                B: x2 over 8 rows x 2 k-halves)
    const int arow = ((lane >> 3) & 1) * 8 + (lane & 7);
    const int akk  = (lane >> 4) * 8;
    const int brow = lane & 7;
    const int bkk  = ((lane >> 3) & 1) * 8;

#pragma unroll
    for (int ks = 0; ks < 4; ks++) {
        int k = ks * 16;
        uint32_t a[2][4];
#pragma unroll
        for (int mi = 0; mi < 2; mi++) {
            uint32_t addr = xbase +
                ((wy * 32 + mi * 16 + arow) * G2_LDA + k + akk) * 2;
            ldm_x4(a[mi][0], a[mi][1], a[mi][2], a[mi][3], addr);
        }
#pragma unroll
        for (int ni = 0; ni < 4; ni++) {
            uint32_t b0, b1;
            uint32_t addr = cbase +
                ((wx * 32 + ni * 8 + brow) * G2_LDA + k + bkk) * 2;
            ldm_x2(b0, b1, addr);
#pragma unroll
            for (int mi = 0; mi < 2; mi++)
                mma_bf16(d[mi][ni], a[mi], b0, b1);
        }
    }

    // epilogue: y = acc + D*u, straight from fragment layout
    const int g  = lane >> 2;
    const int cq = (lane & 3) * 2;
#pragma unroll
    for (int mi = 0; mi < 2; mi++) {
        int r0 = m0 + wy * 32 + mi * 16 + g;
        int r1 = r0 + 8;
#pragma unroll
        for (int ni = 0; ni < 4; ni++) {
            int c = i0 + wx * 32 + ni * 8 + cq;
            float2 dv = *reinterpret_cast<const float2*>(&D[c]);
            float2 u0 = *reinterpret_cast<const float2*>(&u[(size_t)r0 * IDIM + c]);
            float2 u1 = *reinterpret_cast<const float2*>(&u[(size_t)r1 * IDIM + c]);
            float2 o0, o1;
            o0.x = d[mi][ni][0] + dv.x * u0.x;
            o0.y = d[mi][ni][1] + dv.y * u0.y;
            o1.x = d[mi][ni][2] + dv.x * u1.x;
            o1.y = d[mi][ni][3] + dv.y * u1.y;
            *reinterpret_cast<float2*>(&y[(size_t)r0 * IDIM + c]) = o0;
            *reinterpret_cast<float2*>(&y[(size_t)r1 * IDIM + c]) = o1;
        }
    }
}

// ---------------------------------------------------------------------------
extern "C" void kernel_launch(void* const* d_in, const int* in_sizes, int n_in,
                              void* d_out, int out_size) {
    const float* u        = (const float*)d_in[0];
    const float* logA     = (const float*)d_in[1];
    const float* B        = (const float*)d_in[2];
    const float* C        = (const float*)d_in[3];
    const float* D        = (const float*)d_in[4];
    const float* logdelta = (const float*)d_in[5];
    float* y = (float*)d_out;

    cudaFuncSetAttribute(k_gemm1, cudaFuncAttributeMaxDynamicSharedMemorySize, G1_SMEM);
    cudaFuncSetAttribute(k_gemm2, cudaFuncAttributeMaxDynamicSharedMemorySize, G2_SMEM);

    k_setup<<<128, 256>>>(logA, B, C, logdelta);
    k_gemm1<<<BT / 64, 256, G1_SMEM>>>(u);
    k_carry<<<BATCH + 1, NDIM>>>();
    dim3 g2(BT / 128, IDIM / 64);
    k_gemm2<<<g2, 256, G2_SMEM>>>(u, D, y);
}

// round 12
// speedup vs baseline: 1.0725x; 1.0725x over previous
#include <cuda_runtime.h>
#include <cuda_bf16.h>
#include <mma.h>
#include <cstdint>

using namespace nvcuda;

// Problem dims (fixed)
#define BATCH 8
#define TLEN  4096
#define IDIM  1024
#define NDIM  64
#define BT    (BATCH * TLEN)      // 32768
#define CH    64                  // scan chunk length (= K1 M tile)
#define NCH   (TLEN / CH)         // 64 chunks per batch

// ---------------------------------------------------------------------------
// Scratch (device globals; allocation forbidden)
// ---------------------------------------------------------------------------
__device__ __nv_bfloat16 g_Bb[NDIM * IDIM];      // Bbar bf16 [n][k]
__device__ __nv_bfloat16 g_Cb[IDIM * NDIM];      // C bf16 [i][n]
__device__ float g_a[NDIM];                      // A_bar_state
__device__ float g_Bu[(size_t)BT * NDIM];        // locally-scanned x (8 MB)
__device__ float g_end[BATCH * NCH * NDIM];      // chunk-local end states
__device__ float g_carry[BATCH * NCH * NDIM];    // carry-in per chunk
__device__ float g_apow[CH * NDIM];              // a_n^(t+1), t=0..63

// ---------------------------------------------------------------------------
// K0 (fused): blocks 0..63  -> per-n: Bbar=B*softplus(logdelta) bf16, a_n
//             blocks 64..127 -> convert C to bf16
// ---------------------------------------------------------------------------
__global__ void k_setup(const float* __restrict__ logA,
                        const float* __restrict__ B,
                        const float* __restrict__ C,
                        const float* __restrict__ logdelta) {
    if (blockIdx.x < NDIM) {
        int n = blockIdx.x;
        float A = -expf(logA[n]);
        __shared__ float red[256];
        float s = 0.f;
        for (int i = threadIdx.x; i < IDIM; i += 256) {
            float ld = logdelta[i];
            float d  = (ld > 20.f) ? ld : log1pf(expf(ld));
            g_Bb[n * IDIM + i] = __float2bfloat16_rn(B[n * IDIM + i] * d);
            s += expf(d * A);
        }
        red[threadIdx.x] = s;
        __syncthreads();
        for (int o = 128; o > 0; o >>= 1) {
            if (threadIdx.x < o) red[threadIdx.x] += red[threadIdx.x + o];
            __syncthreads();
        }
        if (threadIdx.x == 0) g_a[n] = red[0] * (1.f / IDIM);
    } else {
        int idx = (blockIdx.x - NDIM) * 256 + threadIdx.x;
        float4 v = *reinterpret_cast<const float4*>(C + 4 * (size_t)idx);
        __nv_bfloat162 lo = __floats2bfloat162_rn(v.x, v.y);
        __nv_bfloat162 hi = __floats2bfloat162_rn(v.z, v.w);
        uint2 pk = make_uint2(*reinterpret_cast<unsigned*>(&lo),
                              *reinterpret_cast<unsigned*>(&hi));
        *reinterpret_cast<uint2*>(&g_Cb[4 * (size_t)idx]) = pk;
    }
}

// ---------------------------------------------------------------------------
// K1: wmma GEMM1 + in-smem local scan epilogue. (unchanged from R10)
// ---------------------------------------------------------------------------
#define G1_LDA 72
#define G1_LDY 68
#define G1_AS   0
#define G1_BS   (64 * G1_LDA * 2)            // 9216
#define G1_YBU  0
#define G1_SEG  (64 * G1_LDY * 4)            // 17408
#define G1_SMEM (G1_SEG + 4 * NDIM * 4)      // 18432

__global__ __launch_bounds__(256) void k_gemm1(const float* __restrict__ u) {
    extern __shared__ char smem[];
    __nv_bfloat16* As = reinterpret_cast<__nv_bfloat16*>(smem + G1_AS);
    __nv_bfloat16* Bs = reinterpret_cast<__nv_bfloat16*>(smem + G1_BS);
    float*        Ybu = reinterpret_cast<float*>(smem + G1_YBU);
    float*        seg = reinterpret_cast<float*>(smem + G1_SEG);

    const int tid = threadIdx.x;
    const int wid = tid >> 5;
    const int wy  = wid >> 2;                    // 0..1 -> m offset 32*wy
    const int wx  = wid & 3;                     // 0..3 -> n offset 16*wx
    const int m0  = blockIdx.x * 64;
    const float* ub = &u[(size_t)m0 * IDIM];

    wmma::fragment<wmma::accumulator, 16, 16, 16, float> acc[2];
#pragma unroll
    for (int a = 0; a < 2; a++) wmma::fill_fragment(acc[a], 0.f);

    float4 r[4];
#pragma unroll
    for (int q = 0; q < 4; q++) {
        int idx = tid + 256 * q;
        int row = idx >> 4;
        int k   = (idx & 15) << 2;
        r[q] = *reinterpret_cast<const float4*>(&ub[(size_t)row * IDIM + k]);
    }

    for (int kc = 0; kc < IDIM; kc += 64) {
#pragma unroll
        for (int q = 0; q < 4; q++) {
            int idx = tid + 256 * q;
            int row = idx >> 4;
            int k   = (idx & 15) << 2;
            __nv_bfloat162 lo = __floats2bfloat162_rn(r[q].x, r[q].y);
            __nv_bfloat162 hi = __floats2bfloat162_rn(r[q].z, r[q].w);
            uint2 pk = make_uint2(*reinterpret_cast<unsigned*>(&lo),
                                  *reinterpret_cast<unsigned*>(&hi));
            *reinterpret_cast<uint2*>(&As[row * G1_LDA + k]) = pk;
        }
#pragma unroll
        for (int q = 0; q < 4; q++) {
            int idx = tid + 256 * q;
            int n   = idx >> 4;
            int k   = (idx & 15) << 2;
            uint2 pk = *reinterpret_cast<const uint2*>(&g_Bb[n * IDIM + kc + k]);
            *reinterpret_cast<uint2*>(&Bs[n * G1_LDA + k]) = pk;
        }
        __syncthreads();

        if (kc + 64 < IDIM) {
#pragma unroll
            for (int q = 0; q < 4; q++) {
                int idx = tid + 256 * q;
                int row = idx >> 4;
                int k   = (idx & 15) << 2;
                r[q] = *reinterpret_cast<const float4*>(
                    &ub[(size_t)row * IDIM + kc + 64 + k]);
            }
        }

#pragma unroll
        for (int ks = 0; ks < 4; ks++) {
            int k = ks * 16;
            wmma::fragment<wmma::matrix_a, 16, 16, 16, __nv_bfloat16, wmma::row_major> af[2];
            wmma::fragment<wmma::matrix_b, 16, 16, 16, __nv_bfloat16, wmma::col_major> bf;
#pragma unroll
            for (int mi = 0; mi < 2; mi++)
                wmma::load_matrix_sync(af[mi], &As[(wy * 32 + mi * 16) * G1_LDA + k], G1_LDA);
            wmma::load_matrix_sync(bf, &Bs[(wx * 16) * G1_LDA + k], G1_LDA);
#pragma unroll
            for (int mi = 0; mi < 2; mi++)
                wmma::mma_sync(acc[mi], af[mi], bf, acc[mi]);
        }
        __syncthreads();
    }

#pragma unroll
    for (int mi = 0; mi < 2; mi++)
        wmma::store_matrix_sync(&Ybu[(wy * 32 + mi * 16) * G1_LDY + wx * 16],
                                acc[mi], G1_LDY, wmma::mem_row_major);
    __syncthreads();

    const int n = tid & 63, q = tid >> 6;
    const float a = g_a[n];
    {
        float* p = &Ybu[(q * 16) * G1_LDY + n];
        float x = 0.f;
#pragma unroll
        for (int j = 0; j < 16; j++) {
            x = x * a + p[j * G1_LDY];
            p[j * G1_LDY] = x;
        }
        seg[q * 64 + n] = x;
    }
    __syncthreads();
    if (q > 0) {
        float a16 = a;
#pragma unroll
        for (int s = 0; s < 4; s++) a16 *= a16;   // a^16
        float S = seg[n];
        for (int pp = 1; pp < q; pp++) S = S * a16 + seg[pp * 64 + n];
        float f = S;
        float* p = &Ybu[(q * 16) * G1_LDY + n];
#pragma unroll
        for (int j = 0; j < 16; j++) {
            f *= a;
            p[j * G1_LDY] += f;
        }
    }
    __syncthreads();

#pragma unroll
    for (int qq = 0; qq < 4; qq++) {
        int idx = tid + 256 * qq;
        int row = idx >> 4;
        int c4  = (idx & 15) << 2;
        float4 v = *reinterpret_cast<const float4*>(&Ybu[row * G1_LDY + c4]);
        *reinterpret_cast<float4*>(&g_Bu[(size_t)(m0 + row) * NDIM + c4]) = v;
    }
    if (tid < 64) g_end[blockIdx.x * 64 + tid] = Ybu[63 * G1_LDY + tid];
}

// ---------------------------------------------------------------------------
// Kc: blocks 0..7 -> per-batch carry scan over 64 chunks; block 8 -> apow.
// ---------------------------------------------------------------------------
__global__ void k_carry() {
    int n = threadIdx.x;
    if (blockIdx.x < BATCH) {
        int b = blockIdx.x;
        float e[NCH];
#pragma unroll
        for (int c = 0; c < NCH; c++) e[c] = g_end[(b * NCH + c) * 64 + n];
        float a = g_a[n], aL = a;
#pragma unroll
        for (int s = 0; s < 6; s++) aL *= aL;     // a^64 = a^CH
        float carry = 0.f;
#pragma unroll
        for (int c = 0; c < NCH; c++) {
            g_carry[(b * NCH + c) * 64 + n] = carry;
            carry = carry * aL + e[c];
        }
    } else {
        float a = g_a[n], p = a;
        for (int j = 0; j < CH; j++) {
            g_apow[j * 64 + n] = p;               // a^(j+1)
            p *= a;
        }
    }
}

// ---------------------------------------------------------------------------
// K2: raw mma.sync GEMM2, 128x128 tile, register epilogue (no Ys round-trip).
//   512 threads = 16 warps (4m x 4i); warp tile 32x32 = 2(mi) x 4(ni) m16n8k16.
//   xs[t][n] = x_local + carry[chunk(t)][n]*apow[t%64][n] (bf16 staged in Xs)
//   epilogue: y[r][c] = acc + D[c]*u[r][c] directly from fragment layout.
// smem: Xs[128][72] bf16 (18432) + Cs[128][72] bf16 (18432) = 36864.
// ---------------------------------------------------------------------------
#define G2_LDA 72
#define G2_XS   0
#define G2_CS   18432
#define G2_SMEM 36864

__device__ __forceinline__ void ldm_x4(uint32_t& r0, uint32_t& r1,
                                       uint32_t& r2, uint32_t& r3, uint32_t a) {
    asm volatile("ldmatrix.sync.aligned.m8n8.x4.shared.b16 {%0,%1,%2,%3}, [%4];"
                 : "=r"(r0), "=r"(r1), "=r"(r2), "=r"(r3) : "r"(a));
}
__device__ __forceinline__ void ldm_x2(uint32_t& r0, uint32_t& r1, uint32_t a) {
    asm volatile("ldmatrix.sync.aligned.m8n8.x2.shared.b16 {%0,%1}, [%2];"
                 : "=r"(r0), "=r"(r1) : "r"(a));
}
__device__ __forceinline__ void mma_bf16(float* d, const uint32_t* a,
                                         uint32_t b0, uint32_t b1) {
    asm volatile(
        "mma.sync.aligned.m16n8k16.row.col.f32.bf16.bf16.f32 "
        "{%0,%1,%2,%3}, {%4,%5,%6,%7}, {%8,%9}, {%0,%1,%2,%3};"
        : "+f"(d[0]), "+f"(d[1]), "+f"(d[2]), "+f"(d[3])
        : "r"(a[0]), "r"(a[1]), "r"(a[2]), "r"(a[3]), "r"(b0), "r"(b1));
}

__global__ __launch_bounds__(512, 2) void k_gemm2(const float* __restrict__ u,
                                                  const float* __restrict__ D,
                                                  float* __restrict__ y) {
    extern __shared__ char smem[];
    __nv_bfloat16* Xs = reinterpret_cast<__nv_bfloat16*>(smem + G2_XS);
    __nv_bfloat16* Cs = reinterpret_cast<__nv_bfloat16*>(smem + G2_CS);

    const int tid  = threadIdx.x;
    const int wid  = tid >> 5;
    const int lane = tid & 31;
    const int wy   = wid >> 2;                   // 0..3 -> m offset 32*wy
    const int wx   = wid & 3;                    // 0..3 -> i offset 32*wx
    const int m0   = blockIdx.x * 128;
    const int i0   = blockIdx.y * 128;
    const int chk2 = blockIdx.x * 2;             // first 64-chunk id in tile

    // xs tile: fixup + bf16 convert (4 float4/thread)
#pragma unroll
    for (int q = 0; q < 4; q++) {
        int idx = tid + 512 * q;
        int row = idx >> 4;                      // 0..127
        int c4  = (idx & 15) << 2;
        float4 bu = *reinterpret_cast<const float4*>(
            &g_Bu[(size_t)(m0 + row) * NDIM + c4]);
        float4 ap = *reinterpret_cast<const float4*>(&g_apow[(row & 63) * 64 + c4]);
        float4 cr = *reinterpret_cast<const float4*>(
            &g_carry[(chk2 + (row >> 6)) * 64 + c4]);
        float x0 = bu.x + cr.x * ap.x;
        float x1 = bu.y + cr.y * ap.y;
        float x2 = bu.z + cr.z * ap.z;
        float x3 = bu.w + cr.w * ap.w;
        __nv_bfloat162 lo = __floats2bfloat162_rn(x0, x1);
        __nv_bfloat162 hi = __floats2bfloat162_rn(x2, x3);
        uint2 pk = make_uint2(*reinterpret_cast<unsigned*>(&lo),
                              *reinterpret_cast<unsigned*>(&hi));
        *reinterpret_cast<uint2*>(&Xs[row * G2_LDA + c4]) = pk;
    }
    // C tile: 128 i-rows x 64 n bf16 (4 uint2/thread)
#pragma unroll
    for (int q = 0; q < 4; q++) {
        int idx = tid + 512 * q;
        int i   = idx >> 4;
        int k   = (idx & 15) << 2;
        uint2 pk = *reinterpret_cast<const uint2*>(&g_Cb[(size_t)(i0 + i) * NDIM + k]);
        *reinterpret_cast<uint2*>(&Cs[i * G2_LDA + k]) = pk;
    }
    __syncthreads();

    float d[2][4][4];
#pragma unroll
    for (int mi = 0; mi < 2; mi++)
#pragma unroll
        for (int ni = 0; ni < 4; ni++)
#pragma unroll
            for (int e = 0; e < 4; e++) d[mi][ni][e] = 0.f;

    const uint32_t xbase = (uint32_t)__cvta_generic_to_shared(Xs);
    const uint32_t cbase = (uint32_t)__cvta_generic_to_shared(Cs);
    const int arow = ((lane >> 3) & 1) * 8 + (lane & 7);
    const int akk  = (lane >> 4) * 8;
    const int brow = lane & 7;
    const int bkk  = ((lane >> 3) & 1) * 8;

#pragma unroll
    for (int ks = 0; ks < 4; ks++) {
        int k = ks * 16;
        uint32_t a[2][4];
#pragma unroll
        for (int mi = 0; mi < 2; mi++) {
            uint32_t addr = xbase +
                ((wy * 32 + mi * 16 + arow) * G2_LDA + k + akk) * 2;
            ldm_x4(a[mi][0], a[mi][1], a[mi][2], a[mi][3], addr);
        }
#pragma unroll
        for (int ni = 0; ni < 4; ni++) {
            uint32_t b0, b1;
            uint32_t addr = cbase +
                ((wx * 32 + ni * 8 + brow) * G2_LDA + k + bkk) * 2;
            ldm_x2(b0, b1, addr);
#pragma unroll
            for (int mi = 0; mi < 2; mi++)
                mma_bf16(d[mi][ni], a[mi], b0, b1);
        }
    }

    // epilogue: y = acc + D*u, straight from fragment layout
    const int g  = lane >> 2;
    const int cq = (lane & 3) * 2;
#pragma unroll
    for (int mi = 0; mi < 2; mi++) {
        int r0 = m0 + wy * 32 + mi * 16 + g;
        int r1 = r0 + 8;
#pragma unroll
        for (int ni = 0; ni < 4; ni++) {
            int c = i0 + wx * 32 + ni * 8 + cq;
            float2 dv = *reinterpret_cast<const float2*>(&D[c]);
            float2 u0 = *reinterpret_cast<const float2*>(&u[(size_t)r0 * IDIM + c]);
            float2 u1 = *reinterpret_cast<const float2*>(&u[(size_t)r1 * IDIM + c]);
            float2 o0, o1;
            o0.x = d[mi][ni][0] + dv.x * u0.x;
            o0.y = d[mi][ni][1] + dv.y * u0.y;
            o1.x = d[mi][ni][2] + dv.x * u1.x;
            o1.y = d[mi][ni][3] + dv.y * u1.y;
            *reinterpret_cast<float2*>(&y[(size_t)r0 * IDIM + c]) = o0;
            *reinterpret_cast<float2*>(&y[(size_t)r1 * IDIM + c]) = o1;
        }
    }
}

// ---------------------------------------------------------------------------
extern "C" void kernel_launch(void* const* d_in, const int* in_sizes, int n_in,
                              void* d_out, int out_size) {
    const float* u        = (const float*)d_in[0];
    const float* logA     = (const float*)d_in[1];
    const float* B        = (const float*)d_in[2];
    const float* C        = (const float*)d_in[3];
    const float* D        = (const float*)d_in[4];
    const float* logdelta = (const float*)d_in[5];
    float* y = (float*)d_out;

    cudaFuncSetAttribute(k_gemm1, cudaFuncAttributeMaxDynamicSharedMemorySize, G1_SMEM);
    cudaFuncSetAttribute(k_gemm2, cudaFuncAttributeMaxDynamicSharedMemorySize, G2_SMEM);

    k_setup<<<128, 256>>>(logA, B, C, logdelta);
    k_gemm1<<<BT / 64, 256, G1_SMEM>>>(u);
    k_carry<<<BATCH + 1, NDIM>>>();
    dim3 g2(BT / 128, IDIM / 128);
    k_gemm2<<<g2, 512, G2_SMEM>>>(u, D, y);
}

// round 13
// speedup vs baseline: 1.0957x; 1.0216x over previous
#include <cuda_runtime.h>
#include <cuda_bf16.h>
#include <mma.h>
#include <cstdint>

using namespace nvcuda;

// Problem dims (fixed)
#define BATCH 8
#define TLEN  4096
#define IDIM  1024
#define NDIM  64
#define BT    (BATCH * TLEN)      // 32768
#define CH    64                  // scan chunk length (= K1 M tile)
#define NCH   (TLEN / CH)         // 64 chunks per batch

// ---------------------------------------------------------------------------
// Scratch (device globals; allocation forbidden)
// ---------------------------------------------------------------------------
__device__ __nv_bfloat16 g_Bb[NDIM * IDIM];      // Bbar bf16 [n][k]
__device__ __nv_bfloat16 g_Cb[IDIM * NDIM];      // C bf16 [i][n]
__device__ float g_a[NDIM];                      // A_bar_state
__device__ float g_Bu[(size_t)BT * NDIM];        // locally-scanned x (8 MB)
__device__ float g_end[BATCH * NCH * NDIM];      // chunk-local end states
__device__ float g_carry[BATCH * NCH * NDIM];    // carry-in per chunk
__device__ float g_apow[CH * NDIM];              // a_n^(t+1), t=0..63

// ---------------------------------------------------------------------------
// K0 (fused): blocks 0..63  -> per-n: Bbar=B*softplus(logdelta) bf16, a_n
//             blocks 64..127 -> convert C to bf16
// ---------------------------------------------------------------------------
__global__ void k_setup(const float* __restrict__ logA,
                        const float* __restrict__ B,
                        const float* __restrict__ C,
                        const float* __restrict__ logdelta) {
    if (blockIdx.x < NDIM) {
        int n = blockIdx.x;
        float A = -expf(logA[n]);
        __shared__ float red[256];
        float s = 0.f;
        for (int i = threadIdx.x; i < IDIM; i += 256) {
            float ld = logdelta[i];
            float d  = (ld > 20.f) ? ld : log1pf(expf(ld));
            g_Bb[n * IDIM + i] = __float2bfloat16_rn(B[n * IDIM + i] * d);
            s += expf(d * A);
        }
        red[threadIdx.x] = s;
        __syncthreads();
        for (int o = 128; o > 0; o >>= 1) {
            if (threadIdx.x < o) red[threadIdx.x] += red[threadIdx.x + o];
            __syncthreads();
        }
        if (threadIdx.x == 0) g_a[n] = red[0] * (1.f / IDIM);
    } else {
        int idx = (blockIdx.x - NDIM) * 256 + threadIdx.x;
        float4 v = *reinterpret_cast<const float4*>(C + 4 * (size_t)idx);
        __nv_bfloat162 lo = __floats2bfloat162_rn(v.x, v.y);
        __nv_bfloat162 hi = __floats2bfloat162_rn(v.z, v.w);
        uint2 pk = make_uint2(*reinterpret_cast<unsigned*>(&lo),
                              *reinterpret_cast<unsigned*>(&hi));
        *reinterpret_cast<uint2*>(&g_Cb[4 * (size_t)idx]) = pk;
    }
}

// ---------------------------------------------------------------------------
// K1: wmma GEMM1 + in-smem local scan epilogue.
//   R13: smem ping-pong double buffering — ONE sync per K-chunk; u and Bbar
//   register-prefetched so LDG overlaps MMA.
// ---------------------------------------------------------------------------
#define G1_LDA 72
#define G1_LDY 68
#define G1_AS   0                                 // 2 x 9216
#define G1_BS   (2 * 64 * G1_LDA * 2)             // 18432, 2 x 9216
#define G1_STG  (64 * G1_LDA * 2)                 // stage stride 9216
#define G1_YBU  0
#define G1_SEG  (64 * G1_LDY * 4)                 // 17408
#define G1_SMEM 36864                             // max(4*9216, seg layout)

__global__ __launch_bounds__(256) void k_gemm1(const float* __restrict__ u) {
    extern __shared__ char smem[];
    float*        Ybu = reinterpret_cast<float*>(smem + G1_YBU);
    float*        seg = reinterpret_cast<float*>(smem + G1_SEG);

    const int tid = threadIdx.x;
    const int wid = tid >> 5;
    const int wy  = wid >> 2;                    // 0..1 -> m offset 32*wy
    const int wx  = wid & 3;                     // 0..3 -> n offset 16*wx
    const int m0  = blockIdx.x * 64;
    const float* ub = &u[(size_t)m0 * IDIM];

    // per-thread staging coords
    const int srow = tid >> 2;                   // 0..63 (for idx=tid..tid+768)
    wmma::fragment<wmma::accumulator, 16, 16, 16, float> acc[2];
#pragma unroll
    for (int a = 0; a < 2; a++) wmma::fill_fragment(acc[a], 0.f);

    // prefetch chunk 0 (u) and B chunk 0 into registers
    float4 r[4];
    uint2  bb[4];
#pragma unroll
    for (int q = 0; q < 4; q++) {
        int idx = tid + 256 * q;
        int row = idx >> 4;
        int k   = (idx & 15) << 2;
        r[q]  = *reinterpret_cast<const float4*>(&ub[(size_t)row * IDIM + k]);
        bb[q] = *reinterpret_cast<const uint2*>(&g_Bb[row * IDIM + k]);
    }

    int buf = 0;
    for (int kc = 0; kc < IDIM; kc += 64) {
        __nv_bfloat16* As = reinterpret_cast<__nv_bfloat16*>(smem + G1_AS + buf * G1_STG);
        __nv_bfloat16* Bs = reinterpret_cast<__nv_bfloat16*>(smem + G1_BS + buf * G1_STG);
        // convert prefetched regs -> As/Bs (bf16) of current buffer
#pragma unroll
        for (int q = 0; q < 4; q++) {
            int idx = tid + 256 * q;
            int row = idx >> 4;
            int k   = (idx & 15) << 2;
            __nv_bfloat162 lo = __floats2bfloat162_rn(r[q].x, r[q].y);
            __nv_bfloat162 hi = __floats2bfloat162_rn(r[q].z, r[q].w);
            uint2 pk = make_uint2(*reinterpret_cast<unsigned*>(&lo),
                                  *reinterpret_cast<unsigned*>(&hi));
            *reinterpret_cast<uint2*>(&As[row * G1_LDA + k]) = pk;
            *reinterpret_cast<uint2*>(&Bs[row * G1_LDA + k]) = bb[q];
        }
        __syncthreads();

        // issue next chunk's loads (overlap with MMA below)
        if (kc + 64 < IDIM) {
#pragma unroll
            for (int q = 0; q < 4; q++) {
                int idx = tid + 256 * q;
                int row = idx >> 4;
                int k   = (idx & 15) << 2;
                r[q]  = *reinterpret_cast<const float4*>(
                    &ub[(size_t)row * IDIM + kc + 64 + k]);
                bb[q] = *reinterpret_cast<const uint2*>(
                    &g_Bb[row * IDIM + kc + 64 + k]);
            }
        }

#pragma unroll
        for (int ks = 0; ks < 4; ks++) {
            int k = ks * 16;
            wmma::fragment<wmma::matrix_a, 16, 16, 16, __nv_bfloat16, wmma::row_major> af[2];
            wmma::fragment<wmma::matrix_b, 16, 16, 16, __nv_bfloat16, wmma::col_major> bf;
#pragma unroll
            for (int mi = 0; mi < 2; mi++)
                wmma::load_matrix_sync(af[mi], &As[(wy * 32 + mi * 16) * G1_LDA + k], G1_LDA);
            wmma::load_matrix_sync(bf, &Bs[(wx * 16) * G1_LDA + k], G1_LDA);
#pragma unroll
            for (int mi = 0; mi < 2; mi++)
                wmma::mma_sync(acc[mi], af[mi], bf, acc[mi]);
        }
        buf ^= 1;
    }
    __syncthreads();   // staging dead; Ybu aliases it

#pragma unroll
    for (int mi = 0; mi < 2; mi++)
        wmma::store_matrix_sync(&Ybu[(wy * 32 + mi * 16) * G1_LDY + wx * 16],
                                acc[mi], G1_LDY, wmma::mem_row_major);
    __syncthreads();

    const int n = tid & 63, q = tid >> 6;
    const float a = g_a[n];
    {
        float* p = &Ybu[(q * 16) * G1_LDY + n];
        float x = 0.f;
#pragma unroll
        for (int j = 0; j < 16; j++) {
            x = x * a + p[j * G1_LDY];
            p[j * G1_LDY] = x;
        }
        seg[q * 64 + n] = x;
    }
    __syncthreads();
    if (q > 0) {
        float a16 = a;
#pragma unroll
        for (int s = 0; s < 4; s++) a16 *= a16;   // a^16
        float S = seg[n];
        for (int pp = 1; pp < q; pp++) S = S * a16 + seg[pp * 64 + n];
        float f = S;
        float* p = &Ybu[(q * 16) * G1_LDY + n];
#pragma unroll
        for (int j = 0; j < 16; j++) {
            f *= a;
            p[j * G1_LDY] += f;
        }
    }
    __syncthreads();

#pragma unroll
    for (int qq = 0; qq < 4; qq++) {
        int idx = tid + 256 * qq;
        int row = idx >> 4;
        int c4  = (idx & 15) << 2;
        float4 v = *reinterpret_cast<const float4*>(&Ybu[row * G1_LDY + c4]);
        *reinterpret_cast<float4*>(&g_Bu[(size_t)(m0 + row) * NDIM + c4]) = v;
    }
    if (tid < 64) g_end[blockIdx.x * 64 + tid] = Ybu[63 * G1_LDY + tid];
}

// ---------------------------------------------------------------------------
// Kc: blocks 0..7 -> per-batch carry scan over 64 chunks; block 8 -> apow.
// ---------------------------------------------------------------------------
__global__ void k_carry() {
    int n = threadIdx.x;
    if (blockIdx.x < BATCH) {
        int b = blockIdx.x;
        float e[NCH];
#pragma unroll
        for (int c = 0; c < NCH; c++) e[c] = g_end[(b * NCH + c) * 64 + n];
        float a = g_a[n], aL = a;
#pragma unroll
        for (int s = 0; s < 6; s++) aL *= aL;     // a^64 = a^CH
        float carry = 0.f;
#pragma unroll
        for (int c = 0; c < NCH; c++) {
            g_carry[(b * NCH + c) * 64 + n] = carry;
            carry = carry * aL + e[c];
        }
    } else {
        float a = g_a[n], p = a;
        for (int j = 0; j < CH; j++) {
            g_apow[j * 64 + n] = p;               // a^(j+1)
            p *= a;
        }
    }
}

// ---------------------------------------------------------------------------
// K2: wmma GEMM2 (512 thr, 16 warps 4x4, warp tile 32x32) — R10 config.
//   M tile 128 = two 64-chunks; fixup picks carry per half-tile.
//   xs[t][n] = x_local + carry[chunk(t)][n]*apow[t%64][n]
//   y[m,i]   = sum_n C[i,n]*xs[m,n] + D[i]*u[m,i]
// smem: Xs(18432) + Cs(18432) bf16, aliased by Ys(67584 fp32) post-MMA.
// ---------------------------------------------------------------------------
#define G2_LDA 72
#define G2_LDY 132
#define G2_XS   0
#define G2_CS   18432
#define G2_YS   0
#define G2_SMEM (128 * G2_LDY * 4)               // 67584

__global__ __launch_bounds__(512, 2) void k_gemm2(const float* __restrict__ u,
                                                  const float* __restrict__ D,
                                                  float* __restrict__ y) {
    extern __shared__ char smem[];
    __nv_bfloat16* Xs = reinterpret_cast<__nv_bfloat16*>(smem + G2_XS);
    __nv_bfloat16* Cs = reinterpret_cast<__nv_bfloat16*>(smem + G2_CS);
    float*         Ys = reinterpret_cast<float*>(smem + G2_YS);

    const int tid = threadIdx.x;
    const int wid = tid >> 5;
    const int wy  = wid >> 2;                    // m offset 32*wy
    const int wx  = wid & 3;                     // i offset 32*wx
    const int m0  = blockIdx.x * 128;
    const int i0  = blockIdx.y * 128;
    const int chk2 = blockIdx.x * 2;             // first 64-chunk id in tile

    // xs tile: fixup + bf16 convert (4 float4/thread)
#pragma unroll
    for (int q = 0; q < 4; q++) {
        int idx = tid + 512 * q;
        int row = idx >> 4;                      // 0..127
        int c4  = (idx & 15) << 2;
        float4 bu = *reinterpret_cast<const float4*>(
            &g_Bu[(size_t)(m0 + row) * NDIM + c4]);
        float4 ap = *reinterpret_cast<const float4*>(&g_apow[(row & 63) * 64 + c4]);
        float4 cr = *reinterpret_cast<const float4*>(
            &g_carry[(chk2 + (row >> 6)) * 64 + c4]);
        float x0 = bu.x + cr.x * ap.x;
        float x1 = bu.y + cr.y * ap.y;
        float x2 = bu.z + cr.z * ap.z;
        float x3 = bu.w + cr.w * ap.w;
        __nv_bfloat162 lo = __floats2bfloat162_rn(x0, x1);
        __nv_bfloat162 hi = __floats2bfloat162_rn(x2, x3);
        uint2 pk = make_uint2(*reinterpret_cast<unsigned*>(&lo),
                              *reinterpret_cast<unsigned*>(&hi));
        *reinterpret_cast<uint2*>(&Xs[row * G2_LDA + c4]) = pk;
    }
    // C tile: 128 i-rows x 64 n bf16 (4 uint2/thread)
#pragma unroll
    for (int q = 0; q < 4; q++) {
        int idx = tid + 512 * q;
        int i   = idx >> 4;
        int k   = (idx & 15) << 2;
        uint2 pk = *reinterpret_cast<const uint2*>(&g_Cb[(size_t)(i0 + i) * NDIM + k]);
        *reinterpret_cast<uint2*>(&Cs[i * G2_LDA + k]) = pk;
    }
    __syncthreads();

    wmma::fragment<wmma::accumulator, 16, 16, 16, float> acc[2][2];
#pragma unroll
    for (int a = 0; a < 2; a++)
#pragma unroll
        for (int bb = 0; bb < 2; bb++) wmma::fill_fragment(acc[a][bb], 0.f);

#pragma unroll
    for (int ks = 0; ks < 4; ks++) {
        int k = ks * 16;
        wmma::fragment<wmma::matrix_a, 16, 16, 16, __nv_bfloat16, wmma::row_major> af[2];
        wmma::fragment<wmma::matrix_b, 16, 16, 16, __nv_bfloat16, wmma::col_major> bf[2];
#pragma unroll
        for (int mi = 0; mi < 2; mi++)
            wmma::load_matrix_sync(af[mi], &Xs[(wy * 32 + mi * 16) * G2_LDA + k], G2_LDA);
#pragma unroll
        for (int ni = 0; ni < 2; ni++)
            wmma::load_matrix_sync(bf[ni], &Cs[(wx * 32 + ni * 16) * G2_LDA + k], G2_LDA);
#pragma unroll
        for (int mi = 0; mi < 2; mi++)
#pragma unroll
            for (int ni = 0; ni < 2; ni++)
                wmma::mma_sync(acc[mi][ni], af[mi], bf[ni], acc[mi][ni]);
    }
    __syncthreads();   // Xs/Cs dead; Ys aliases them

#pragma unroll
    for (int mi = 0; mi < 2; mi++)
#pragma unroll
        for (int ni = 0; ni < 2; ni++)
            wmma::store_matrix_sync(&Ys[(wy * 32 + mi * 16) * G2_LDY + wx * 32 + ni * 16],
                                    acc[mi][ni], G2_LDY, wmma::mem_row_major);
    __syncthreads();

    // epilogue: y = Ys + D*u  (8 float4/thread)
#pragma unroll 2
    for (int q = 0; q < 8; q++) {
        int idx = tid + 512 * q;
        int row = idx >> 5;
        int col = (idx & 31) << 2;
        int grow = m0 + row;
        int gcol = i0 + col;
        float4 uv = *reinterpret_cast<const float4*>(&u[(size_t)grow * IDIM + gcol]);
        float4 dv = *reinterpret_cast<const float4*>(&D[gcol]);
        float4 sv = *reinterpret_cast<const float4*>(&Ys[row * G2_LDY + col]);
        float4 o;
        o.x = sv.x + dv.x * uv.x;
        o.y = sv.y + dv.y * uv.y;
        o.z = sv.z + dv.z * uv.z;
        o.w = sv.w + dv.w * uv.w;
        *reinterpret_cast<float4*>(&y[(size_t)grow * IDIM + gcol]) = o;
    }
}

// ---------------------------------------------------------------------------
extern "C" void kernel_launch(void* const* d_in, const int* in_sizes, int n_in,
                              void* d_out, int out_size) {
    const float* u        = (const float*)d_in[0];
    const float* logA     = (const float*)d_in[1];
    const float* B        = (const float*)d_in[2];
    const float* C        = (const float*)d_in[3];
    const float* D        = (const float*)d_in[4];
    const float* logdelta = (const float*)d_in[5];
    float* y = (float*)d_out;

    cudaFuncSetAttribute(k_gemm1, cudaFuncAttributeMaxDynamicSharedMemorySize, G1_SMEM);
    cudaFuncSetAttribute(k_gemm2, cudaFuncAttributeMaxDynamicSharedMemorySize, G2_SMEM);

    k_setup<<<128, 256>>>(logA, B, C, logdelta);
    k_gemm1<<<BT / 64, 256, G1_SMEM>>>(u);
    k_carry<<<BATCH + 1, NDIM>>>();
    dim3 g2(BT / 128, IDIM / 128);
    k_gemm2<<<g2, 512, G2_SMEM>>>(u, D, y);
}